// round 3
// baseline (speedup 1.0000x reference)
#include <cuda_runtime.h>
#include <cstdint>

#define B_   4
#define T_   2048
#define D_   2048
#define H_   16
#define HD_  128
#define NTOK (B_*T_)

// Scratch (device globals: allocation inside kernel_launch is forbidden)
__device__ float g_Q [NTOK*(size_t)D_];
__device__ float g_K [NTOK*(size_t)D_];
__device__ float g_V [NTOK*(size_t)D_];
__device__ float g_AO[NTOK*(size_t)D_];

// ---------------- packed f32x2 helpers ----------------
__device__ __forceinline__ void ffma2(unsigned long long& d, unsigned long long a, unsigned long long b) {
    asm("fma.rn.f32x2 %0, %1, %2, %0;" : "+l"(d) : "l"(a), "l"(b));
}
__device__ __forceinline__ unsigned long long fmul2(unsigned long long a, unsigned long long b) {
    unsigned long long r;
    asm("mul.rn.f32x2 %0, %1, %2;" : "=l"(r) : "l"(a), "l"(b));
    return r;
}
__device__ __forceinline__ unsigned long long dup2(float x) {
    unsigned long long r;
    asm("mov.b64 %0, {%1, %1};" : "=l"(r) : "r"(__float_as_uint(x)));
    return r;
}
__device__ __forceinline__ float2 unpk(unsigned long long v) {
    float2 f;
    unsigned lo, hi;
    asm("mov.b64 {%0, %1}, %2;" : "=r"(lo), "=r"(hi) : "l"(v));
    f.x = __uint_as_float(lo);
    f.y = __uint_as_float(hi);
    return f;
}

// ---------------- GEMM core: C[128,128] tile of A[M,2048] @ W[2048,2048] ----------------
// 128x128 block tile, BK=16, 256 threads, 8x8 per-thread microtile as 8x4 f32x2 accs.
// A tile stored duplicated along M so the FFMA2 "a" operand is a direct LDS pair.
__device__ __forceinline__
void gemm_tile(const float* __restrict__ A, const float* __restrict__ W,
               const float* __restrict__ bias, float* __restrict__ C,
               int bx, int by)
{
    const int K = D_, N = D_;
    __shared__ float As2[16][256];   // [k][2m] duplicated
    __shared__ float Bs [16][128];

    const int tid = threadIdx.x;
    const int tx = tid & 15, ty = tid >> 4;

    const float* Ab = A + (size_t)by * 128 * K;
    const float* Wb = W + (size_t)bx * 128;

    const int ar = tid >> 2;          // A: row 0..63 (+64)
    const int ak = (tid & 3) << 2;    //    k offset 0,4,8,12
    const int br = tid >> 5;          // B: row 0..7 (+8)
    const int bc = (tid & 31) << 2;   //    col offset

    unsigned long long acc[8][4];
#pragma unroll
    for (int i = 0; i < 8; i++)
#pragma unroll
        for (int j = 0; j < 4; j++) acc[i][j] = 0ull;

    for (int k0 = 0; k0 < K; k0 += 16) {
#pragma unroll
        for (int u = 0; u < 2; u++) {
            int r = ar + u * 64;
            float4 v = *reinterpret_cast<const float4*>(Ab + (size_t)r * K + k0 + ak);
            As2[ak+0][2*r] = v.x; As2[ak+0][2*r+1] = v.x;
            As2[ak+1][2*r] = v.y; As2[ak+1][2*r+1] = v.y;
            As2[ak+2][2*r] = v.z; As2[ak+2][2*r+1] = v.z;
            As2[ak+3][2*r] = v.w; As2[ak+3][2*r+1] = v.w;
        }
#pragma unroll
        for (int u = 0; u < 2; u++) {
            int r = br + u * 8;
            *reinterpret_cast<float4*>(&Bs[r][bc]) =
                *reinterpret_cast<const float4*>(Wb + (size_t)(k0 + r) * N + bc);
        }
        __syncthreads();
#pragma unroll
        for (int k = 0; k < 16; k++) {
            // rows 4ty..4ty+3 and 64+4ty..+3 (duplicated pairs)
            ulonglong2 a01 = *reinterpret_cast<const ulonglong2*>(&As2[k][8*ty]);
            ulonglong2 a23 = *reinterpret_cast<const ulonglong2*>(&As2[k][8*ty + 4]);
            ulonglong2 a45 = *reinterpret_cast<const ulonglong2*>(&As2[k][128 + 8*ty]);
            ulonglong2 a67 = *reinterpret_cast<const ulonglong2*>(&As2[k][128 + 8*ty + 4]);
            // cols 4tx..+3 and 64+4tx..+3 (natural pairs)
            ulonglong2 bA  = *reinterpret_cast<const ulonglong2*>(&Bs[k][4*tx]);
            ulonglong2 bB  = *reinterpret_cast<const ulonglong2*>(&Bs[k][64 + 4*tx]);
            unsigned long long ad[8] = {a01.x, a01.y, a23.x, a23.y, a45.x, a45.y, a67.x, a67.y};
            unsigned long long b2[4] = {bA.x, bA.y, bB.x, bB.y};
#pragma unroll
            for (int i = 0; i < 8; i++) {
#pragma unroll
                for (int j = 0; j < 4; j++)
                    ffma2(acc[i][j], ad[i], b2[j]);
            }
        }
        __syncthreads();
    }

#pragma unroll
    for (int i = 0; i < 8; i++) {
        int r = by*128 + ((i < 4) ? (4*ty + i) : (64 + 4*ty + (i - 4)));
        float* Crow = C + (size_t)r * N + (size_t)bx * 128;
#pragma unroll
        for (int half = 0; half < 2; half++) {
            int c = half ? (64 + 4*tx) : (4*tx);
            float2 p0 = unpk(acc[i][half*2 + 0]);
            float2 p1 = unpk(acc[i][half*2 + 1]);
            float4 v = make_float4(p0.x, p0.y, p1.x, p1.y);
            if (bias) {
                const float* bp = bias + (size_t)bx * 128 + c;
                v.x += bp[0]; v.y += bp[1]; v.z += bp[2]; v.w += bp[3];
            }
            *reinterpret_cast<float4*>(Crow + c) = v;
        }
    }
}

// Fused QKV: gridDim.z = 3 selects (Wq->g_Q, Wk->g_K, Wv->g_V)
__global__ __launch_bounds__(256, 2)
void gemm_qkv(const float* __restrict__ x,
              const float* __restrict__ Wq, const float* __restrict__ Wk,
              const float* __restrict__ Wv)
{
    const float* W;
    float* C;
    if (blockIdx.z == 0)      { W = Wq; C = g_Q; }
    else if (blockIdx.z == 1) { W = Wk; C = g_K; }
    else                      { W = Wv; C = g_V; }
    gemm_tile(x, W, nullptr, C, blockIdx.x, blockIdx.y);
}

// Output projection: out = AO @ Wo + bo
__global__ __launch_bounds__(256, 2)
void gemm_out(const float* __restrict__ Wo, const float* __restrict__ bo,
              float* __restrict__ out)
{
    gemm_tile(g_AO, Wo, bo, out, blockIdx.x, blockIdx.y);
}

// ---------------- Flash attention (causal), fp32 + f32x2 ----------------
// Per CTA: 64 q-rows of one (b,h). 256 threads as 16x16. Thread (ty,tx):
//   S phase : q-rows 4ty..+3, k-cols 4tx..+3, packed along K (both ops LDS.64)
//   PV phase: same q-rows, out-cols {4tx..+3, 64+4tx..+3}, P duplicated in smem
#define QK_STR 130   // padded row stride for Qs/Ks/Sd (conflict-free LDS.64)
#define ATTN_SMEM_FLOATS (2*64*QK_STR + 64*128 + 64*QK_STR)
#define SCALE_ 0.08838834764831845f   // 1/sqrt(128)

__global__ __launch_bounds__(256, 1)
void attn_kernel()
{
    extern __shared__ float sm[];
    float* Qs = sm;                          // 64 x 130
    float* Ks = sm + 64*QK_STR;              // 64 x 130
    float* Vs = sm + 2*64*QK_STR;            // 64 x 128
    float* Sd = sm + 2*64*QK_STR + 64*128;   // 64 x 130 (P duplicated)

    const int tid = threadIdx.x;
    const int tx = tid & 15, ty = tid >> 4;
    const int qb = blockIdx.x;               // q block 0..31
    const int bh = blockIdx.y;               // 0..63
    const int b  = bh >> 4, h = bh & 15;
    const int q0 = qb * 64;
    const size_t headoff = (size_t)b * T_ * D_ + (size_t)h * HD_;

    // Load + pre-scale Q tile (64x128)
    {
        const float* Qg = g_Q + headoff + (size_t)q0 * D_;
#pragma unroll
        for (int u = 0; u < 16; u++) {
            int idx = u*256 + tid;
            int r = idx >> 6, c2 = idx & 63;
            float2 v = *reinterpret_cast<const float2*>(Qg + (size_t)r * D_ + 2*c2);
            Qs[r*QK_STR + 2*c2]     = v.x * SCALE_;
            Qs[r*QK_STR + 2*c2 + 1] = v.y * SCALE_;
        }
    }

    unsigned long long o2[4][4];
    float m[4], l[4];
#pragma unroll
    for (int i = 0; i < 4; i++) {
        m[i] = -1e30f; l[i] = 0.f;
#pragma unroll
        for (int j = 0; j < 4; j++) o2[i][j] = 0ull;
    }

    for (int jb = 0; jb <= qb; jb++) {
        __syncthreads();   // previous PV done with Vs/Sd
        {
            const float* Kg = g_K + headoff + (size_t)jb * 64 * D_;
            const float* Vg = g_V + headoff + (size_t)jb * 64 * D_;
#pragma unroll
            for (int u = 0; u < 16; u++) {
                int idx = u*256 + tid;
                int r = idx >> 6, c2 = idx & 63;
                float2 v = *reinterpret_cast<const float2*>(Kg + (size_t)r * D_ + 2*c2);
                Ks[r*QK_STR + 2*c2]     = v.x;
                Ks[r*QK_STR + 2*c2 + 1] = v.y;
            }
#pragma unroll
            for (int u = 0; u < 8; u++) {
                int idx = u*256 + tid;
                int r = idx >> 5, c4 = idx & 31;
                *reinterpret_cast<float4*>(&Vs[r*128 + 4*c4]) =
                    *reinterpret_cast<const float4*>(Vg + (size_t)r * D_ + 4*c4);
            }
        }
        __syncthreads();

        // ---- S = Qs @ Ks^T  (packed along K) ----
        unsigned long long s2[4][4];
#pragma unroll
        for (int i = 0; i < 4; i++)
#pragma unroll
            for (int j = 0; j < 4; j++) s2[i][j] = 0ull;

#pragma unroll 4
        for (int kk = 0; kk < 64; kk++) {
            unsigned long long qa[4], kb[4];
#pragma unroll
            for (int i = 0; i < 4; i++)
                qa[i] = *reinterpret_cast<const unsigned long long*>(&Qs[(4*ty + i)*QK_STR + 2*kk]);
#pragma unroll
            for (int j = 0; j < 4; j++)
                kb[j] = *reinterpret_cast<const unsigned long long*>(&Ks[(4*tx + j)*QK_STR + 2*kk]);
#pragma unroll
            for (int i = 0; i < 4; i++)
#pragma unroll
                for (int j = 0; j < 4; j++)
                    ffma2(s2[i][j], qa[i], kb[j]);
        }

        float s[4][4];
#pragma unroll
        for (int i = 0; i < 4; i++)
#pragma unroll
            for (int j = 0; j < 4; j++) {
                float2 p = unpk(s2[i][j]);
                s[i][j] = p.x + p.y;
            }

        if (jb == qb) {   // diagonal block: causal mask (k_idx > q_idx)
#pragma unroll
            for (int i = 0; i < 4; i++)
#pragma unroll
                for (int j = 0; j < 4; j++)
                    if (4*tx + j > 4*ty + i) s[i][j] = -1e30f;
        }

        // ---- online softmax + write duplicated P ----
#pragma unroll
        for (int i = 0; i < 4; i++) {
            float rmax = fmaxf(fmaxf(s[i][0], s[i][1]), fmaxf(s[i][2], s[i][3]));
#pragma unroll
            for (int off = 1; off < 16; off <<= 1)
                rmax = fmaxf(rmax, __shfl_xor_sync(0xffffffffu, rmax, off));
            float mn   = fmaxf(m[i], rmax);
            float corr = __expf(m[i] - mn);
            float p0 = __expf(s[i][0] - mn);
            float p1 = __expf(s[i][1] - mn);
            float p2 = __expf(s[i][2] - mn);
            float p3 = __expf(s[i][3] - mn);
            float rsum = p0 + p1 + p2 + p3;
#pragma unroll
            for (int off = 1; off < 16; off <<= 1)
                rsum += __shfl_xor_sync(0xffffffffu, rsum, off);
            l[i] = l[i]*corr + rsum;
            m[i] = mn;
            unsigned long long cd = dup2(corr);
#pragma unroll
            for (int j = 0; j < 4; j++) o2[i][j] = fmul2(o2[i][j], cd);

            float* srow = &Sd[(4*ty + i)*QK_STR];
            *reinterpret_cast<unsigned long long*>(&srow[2*(4*tx + 0)]) = dup2(p0);
            *reinterpret_cast<unsigned long long*>(&srow[2*(4*tx + 1)]) = dup2(p1);
            *reinterpret_cast<unsigned long long*>(&srow[2*(4*tx + 2)]) = dup2(p2);
            *reinterpret_cast<unsigned long long*>(&srow[2*(4*tx + 3)]) = dup2(p3);
        }
        __syncthreads();

        // ---- O += P @ V  (packed along hd) ----
#pragma unroll 2
        for (int kk = 0; kk < 64; kk++) {
            unsigned long long pd[4];
#pragma unroll
            for (int i = 0; i < 4; i++)
                pd[i] = *reinterpret_cast<const unsigned long long*>(&Sd[(4*ty + i)*QK_STR + 2*kk]);
            ulonglong2 vA = *reinterpret_cast<const ulonglong2*>(&Vs[kk*128 + 4*tx]);
            ulonglong2 vB = *reinterpret_cast<const ulonglong2*>(&Vs[kk*128 + 64 + 4*tx]);
#pragma unroll
            for (int i = 0; i < 4; i++) {
                ffma2(o2[i][0], pd[i], vA.x);
                ffma2(o2[i][1], pd[i], vA.y);
                ffma2(o2[i][2], pd[i], vB.x);
                ffma2(o2[i][3], pd[i], vB.y);
            }
        }
    }

    // ---- normalize + store into (B,T,H*hd) layout ----
    float* Og = g_AO + headoff + (size_t)q0 * D_;
#pragma unroll
    for (int i = 0; i < 4; i++) {
        float inv = 1.0f / l[i];
        int r = 4*ty + i;
#pragma unroll
        for (int half = 0; half < 2; half++) {
            int c = half ? (64 + 4*tx) : (4*tx);
            float2 p0 = unpk(o2[i][half*2 + 0]);
            float2 p1 = unpk(o2[i][half*2 + 1]);
            float4 v = make_float4(p0.x*inv, p0.y*inv, p1.x*inv, p1.y*inv);
            *reinterpret_cast<float4*>(Og + (size_t)r * D_ + c) = v;
        }
    }
}

// ---------------- launch ----------------
extern "C" void kernel_launch(void* const* d_in, const int* in_sizes, int n_in,
                              void* d_out, int out_size)
{
    (void)in_sizes; (void)n_in; (void)out_size;
    const float* x  = (const float*)d_in[0];
    const float* Wq = (const float*)d_in[1];
    const float* Wk = (const float*)d_in[2];
    const float* Wv = (const float*)d_in[3];
    const float* Wo = (const float*)d_in[4];
    const float* bo = (const float*)d_in[5];
    float* out = (float*)d_out;

    const int attn_smem = ATTN_SMEM_FLOATS * (int)sizeof(float);   // 132,608 B
    cudaFuncSetAttribute(attn_kernel, cudaFuncAttributeMaxDynamicSharedMemorySize, attn_smem);

    dim3 gblk(256);
    dim3 gqkv(D_/128, NTOK/128, 3);   // (16, 64, 3) fused QKV
    dim3 gout(D_/128, NTOK/128);      // (16, 64)

    gemm_qkv<<<gqkv, gblk>>>(x, Wq, Wk, Wv);
    attn_kernel<<<dim3(T_/64, B_*H_), 256, attn_smem>>>();
    gemm_out<<<gout, gblk>>>(Wo, bo, out);
}

// round 7
// speedup vs baseline: 2.9658x; 2.9658x over previous
#include <cuda_runtime.h>
#include <cuda_bf16.h>
#include <cstdint>

#define B_   4
#define T_   2048
#define D_   2048
#define H_   16
#define HD_  128
#define NTOK (B_*T_)
#define NELEM ((size_t)NTOK*D_)
#define WELEM ((size_t)D_*D_)

// ---------------- device scratch ----------------
__device__ float g_Q [NELEM];
__device__ float g_K [NELEM];
__device__ float g_V [NELEM];
__device__ float g_AO[NELEM];
__device__ __nv_bfloat16 g_xhi[NELEM];
__device__ __nv_bfloat16 g_xlo[NELEM];
__device__ __nv_bfloat16 g_aohi[NELEM];
__device__ __nv_bfloat16 g_aolo[NELEM];
__device__ __nv_bfloat16 g_wth[4*WELEM];   // transposed hi: [which][N][K]
__device__ __nv_bfloat16 g_wtl[4*WELEM];   // transposed lo

// ---------------- PTX helpers (compute_103-safe: no tcgen05/TMEM) ----------------
__device__ __forceinline__ uint32_t smem_u32(const void* p) {
    uint32_t a;
    asm("{ .reg .u64 t; cvta.to.shared.u64 t, %1; cvt.u32.u64 %0, t; }" : "=r"(a) : "l"(p));
    return a;
}
__device__ __forceinline__ void cp16(uint32_t sa, const void* ga) {
    asm volatile("cp.async.ca.shared.global [%0], [%1], 16;" :: "r"(sa), "l"(ga));
}
__device__ __forceinline__ void cp_commit() {
    asm volatile("cp.async.commit_group;" ::: "memory");
}
template <int N>
__device__ __forceinline__ void cp_wait() {
    asm volatile("cp.async.wait_group %0;" :: "n"(N) : "memory");
}
__device__ __forceinline__ void ldsm4(uint32_t* r, uint32_t addr) {
    asm volatile("ldmatrix.sync.aligned.m8n8.x4.shared.b16 {%0,%1,%2,%3}, [%4];"
                 : "=r"(r[0]), "=r"(r[1]), "=r"(r[2]), "=r"(r[3]) : "r"(addr));
}
__device__ __forceinline__ void mma_bf16(float* d, const uint32_t* a, uint32_t b0, uint32_t b1) {
    asm volatile("mma.sync.aligned.m16n8k16.row.col.f32.bf16.bf16.f32 "
                 "{%0,%1,%2,%3}, {%4,%5,%6,%7}, {%8,%9}, {%0,%1,%2,%3};"
                 : "+f"(d[0]), "+f"(d[1]), "+f"(d[2]), "+f"(d[3])
                 : "r"(a[0]), "r"(a[1]), "r"(a[2]), "r"(a[3]), "r"(b0), "r"(b1));
}

// ---------------- fp32 -> bf16 hi/lo split (elementwise) ----------------
__device__ __forceinline__ void split1(float v, __nv_bfloat16& h, __nv_bfloat16& l) {
    h = __float2bfloat16(v);
    l = __float2bfloat16(v - __bfloat162float(h));
}
__global__ void fsplit_x(const float* __restrict__ in) {
    size_t i = (size_t)(blockIdx.x * blockDim.x + threadIdx.x) * 4;
    float4 v = *reinterpret_cast<const float4*>(in + i);
    __nv_bfloat16 h0,h1,h2,h3,l0,l1,l2,l3;
    split1(v.x,h0,l0); split1(v.y,h1,l1); split1(v.z,h2,l2); split1(v.w,h3,l3);
    __nv_bfloat162* hp = reinterpret_cast<__nv_bfloat162*>(g_xhi + i);
    __nv_bfloat162* lp = reinterpret_cast<__nv_bfloat162*>(g_xlo + i);
    __nv_bfloat162 a; a.x=h0; a.y=h1; hp[0]=a; a.x=h2; a.y=h3; hp[1]=a;
    __nv_bfloat162 b; b.x=l0; b.y=l1; lp[0]=b; b.x=l2; b.y=l3; lp[1]=b;
}
__global__ void fsplit_ao() {
    size_t i = (size_t)(blockIdx.x * blockDim.x + threadIdx.x) * 4;
    float4 v = *reinterpret_cast<const float4*>(g_AO + i);
    __nv_bfloat16 h0,h1,h2,h3,l0,l1,l2,l3;
    split1(v.x,h0,l0); split1(v.y,h1,l1); split1(v.z,h2,l2); split1(v.w,h3,l3);
    __nv_bfloat162* hp = reinterpret_cast<__nv_bfloat162*>(g_aohi + i);
    __nv_bfloat162* lp = reinterpret_cast<__nv_bfloat162*>(g_aolo + i);
    __nv_bfloat162 a; a.x=h0; a.y=h1; hp[0]=a; a.x=h2; a.y=h3; hp[1]=a;
    __nv_bfloat162 b; b.x=l0; b.y=l1; lp[0]=b; b.x=l2; b.y=l3; lp[1]=b;
}

// ---------------- weight transpose + split: W[K,N] -> Wt hi/lo [N,K] ----------------
__global__ void wsplit(const float* __restrict__ Wq, const float* __restrict__ Wk,
                       const float* __restrict__ Wv, const float* __restrict__ Wo) {
    const float* W;
    int z = blockIdx.z;
    if (z == 0) W = Wq; else if (z == 1) W = Wk; else if (z == 2) W = Wv; else W = Wo;
    __nv_bfloat16* th = g_wth + (size_t)z * WELEM;
    __nv_bfloat16* tl = g_wtl + (size_t)z * WELEM;

    __shared__ float t[32][33];
    int tx = threadIdx.x & 31, ty = threadIdx.x >> 5;   // 32 x 8
    int x0 = blockIdx.x * 32, y0 = blockIdx.y * 32;
#pragma unroll
    for (int i = 0; i < 4; i++)
        t[ty + 8*i][tx] = W[(size_t)(y0 + ty + 8*i) * D_ + x0 + tx];
    __syncthreads();
#pragma unroll
    for (int i = 0; i < 4; i++) {
        int n = x0 + ty + 8*i, k = y0 + tx;
        float v = t[tx][ty + 8*i];
        __nv_bfloat16 h, l;
        split1(v, h, l);
        th[(size_t)n * D_ + k] = h;
        tl[(size_t)n * D_ + k] = l;
    }
}

// ---------------- HMMA GEMM core ----------------
// C[128,128] = (Ah+Al)[128,2048] @ (Bh+Bl)t ; 512 thr, 16 warps (4x4), warp 32x32.
// smem tiles 128 x 64 bf16 with padded stride 72 elems (144B) -> conflict-free ldmatrix.
#define GST_B    144                      // smem row stride bytes
#define GTILE_B  (128*GST_B)              // 18432
#define GSTAGE_B (4*GTILE_B)              // Ah, Al, Bh, Bl = 73728
#define GSMEM_TOT (2*GSTAGE_B)            // 147456

__device__ __forceinline__
void gemm_hmma_core(const __nv_bfloat16* __restrict__ Ah, const __nv_bfloat16* __restrict__ Al,
                    const __nv_bfloat16* __restrict__ Bh, const __nv_bfloat16* __restrict__ Bl,
                    const float* __restrict__ bias, float* __restrict__ C,
                    int bx, int by)
{
    extern __shared__ char smem[];
    const uint32_t sb = smem_u32(smem);
    const int tid = threadIdx.x;
    const int wid = tid >> 5, l = tid & 31;
    const int wm = wid >> 2, wn = wid & 3;
    const int m0 = by * 128, n0 = bx * 128;

    const __nv_bfloat16* src[4] = {
        Ah + (size_t)m0 * D_, Al + (size_t)m0 * D_,
        Bh + (size_t)n0 * D_, Bl + (size_t)n0 * D_ };

    // per-lane ldmatrix offsets
    const int a_row = (l & 7) + ((l >> 3) & 1) * 8;
    const int a_c8  = ((l >> 4) & 1) * 8;
    const int b_row = (l & 7) + ((l >> 4) & 1) * 8;
    const int b_c8  = ((l >> 3) & 1) * 8;
    uint32_t aoff[2], boff[2];
#pragma unroll
    for (int i = 0; i < 2; i++) aoff[i] = (32*wm + 16*i + a_row) * GST_B + a_c8 * 2;
#pragma unroll
    for (int p = 0; p < 2; p++) boff[p] = (32*wn + 16*p + b_row) * GST_B + b_c8 * 2;

    float d[2][4][4];
#pragma unroll
    for (int i = 0; i < 2; i++)
#pragma unroll
        for (int j = 0; j < 4; j++)
#pragma unroll
            for (int q = 0; q < 4; q++) d[i][j][q] = 0.f;

    auto issue = [&](int ch) {
        const uint32_t s0 = sb + (ch & 1) * GSTAGE_B;
        const int k0 = ch * 64;
#pragma unroll
        for (int a = 0; a < 4; a++) {
#pragma unroll
            for (int h = 0; h < 2; h++) {
                int s = tid + h * 512;
                int row = s >> 3, c = s & 7;
                cp16(s0 + a*GTILE_B + row*GST_B + c*16,
                     src[a] + (size_t)row * D_ + k0 + c*8);
            }
        }
        cp_commit();
    };

    issue(0);
#pragma unroll 1
    for (int ch = 0; ch < 32; ch++) {
        if (ch < 31) { issue(ch + 1); cp_wait<1>(); }
        else         { cp_wait<0>(); }
        __syncthreads();

        const uint32_t s0 = sb + (ch & 1) * GSTAGE_B;
#pragma unroll
        for (int ks = 0; ks < 4; ks++) {
            const int kb = ks * 32;   // 16 bf16 * 2B
            uint32_t AH[2][4], AL[2][4], BH[2][4], BL[2][4];
#pragma unroll
            for (int i = 0; i < 2; i++) {
                ldsm4(AH[i], s0 +              aoff[i] + kb);
                ldsm4(AL[i], s0 +   GTILE_B +  aoff[i] + kb);
            }
#pragma unroll
            for (int p = 0; p < 2; p++) {
                ldsm4(BH[p], s0 + 2*GTILE_B + boff[p] + kb);
                ldsm4(BL[p], s0 + 3*GTILE_B + boff[p] + kb);
            }
#pragma unroll
            for (int i = 0; i < 2; i++) {
#pragma unroll
                for (int j = 0; j < 4; j++) {
                    const int p = j >> 1, r = (j & 1) * 2;
                    mma_bf16(d[i][j], AH[i], BH[p][r], BH[p][r+1]);
                    mma_bf16(d[i][j], AH[i], BL[p][r], BL[p][r+1]);
                    mma_bf16(d[i][j], AL[i], BH[p][r], BH[p][r+1]);
                }
            }
        }
        __syncthreads();
    }

    // epilogue: fragment layout -> C
    const int gid = l >> 2, tig = l & 3;
#pragma unroll
    for (int i = 0; i < 2; i++) {
#pragma unroll
        for (int j = 0; j < 4; j++) {
            int row = m0 + 32*wm + 16*i + gid;
            int col = n0 + 32*wn + 8*j + 2*tig;
            float2 v0 = make_float2(d[i][j][0], d[i][j][1]);
            float2 v1 = make_float2(d[i][j][2], d[i][j][3]);
            if (bias) {
                const float2 bb = *reinterpret_cast<const float2*>(bias + col);
                v0.x += bb.x; v0.y += bb.y;
                v1.x += bb.x; v1.y += bb.y;
            }
            *reinterpret_cast<float2*>(C + (size_t)row * D_ + col)       = v0;
            *reinterpret_cast<float2*>(C + (size_t)(row + 8) * D_ + col) = v1;
        }
    }
}

__global__ __launch_bounds__(512, 1)
void gemm_qkv_tc() {
    const int z = blockIdx.z;
    float* C = (z == 0) ? g_Q : (z == 1) ? g_K : g_V;
    gemm_hmma_core(g_xhi, g_xlo, g_wth + (size_t)z * WELEM, g_wtl + (size_t)z * WELEM,
                   nullptr, C, blockIdx.x, blockIdx.y);
}
__global__ __launch_bounds__(512, 1)
void gemm_out_tc(const float* __restrict__ bo, float* __restrict__ out) {
    gemm_hmma_core(g_aohi, g_aolo, g_wth + 3 * WELEM, g_wtl + 3 * WELEM,
                   bo, out, blockIdx.x, blockIdx.y);
}

// ---------------- packed f32x2 helpers (attention) ----------------
__device__ __forceinline__ void ffma2(unsigned long long& d, unsigned long long a, unsigned long long b) {
    asm("fma.rn.f32x2 %0, %1, %2, %0;" : "+l"(d) : "l"(a), "l"(b));
}
__device__ __forceinline__ unsigned long long fmul2(unsigned long long a, unsigned long long b) {
    unsigned long long r;
    asm("mul.rn.f32x2 %0, %1, %2;" : "=l"(r) : "l"(a), "l"(b));
    return r;
}
__device__ __forceinline__ unsigned long long dup2(float x) {
    unsigned long long r;
    asm("mov.b64 %0, {%1, %1};" : "=l"(r) : "r"(__float_as_uint(x)));
    return r;
}
__device__ __forceinline__ float2 unpk(unsigned long long v) {
    float2 f; unsigned lo, hi;
    asm("mov.b64 {%0, %1}, %2;" : "=r"(lo), "=r"(hi) : "l"(v));
    f.x = __uint_as_float(lo); f.y = __uint_as_float(hi);
    return f;
}

// ---------------- Flash attention (causal), fp32 + f32x2 (R3-proven) ----------------
#define QK_STR 130
#define ATTN_SMEM_FLOATS (2*64*QK_STR + 64*128 + 64*QK_STR)
#define SCALE_ 0.08838834764831845f

__global__ __launch_bounds__(256, 1)
void attn_kernel()
{
    extern __shared__ float sm[];
    float* Qs = sm;
    float* Ks = sm + 64*QK_STR;
    float* Vs = sm + 2*64*QK_STR;
    float* Sd = sm + 2*64*QK_STR + 64*128;

    const int tid = threadIdx.x;
    const int tx = tid & 15, ty = tid >> 4;
    const int qb = blockIdx.x;
    const int bh = blockIdx.y;
    const int b  = bh >> 4, h = bh & 15;
    const int q0 = qb * 64;
    const size_t headoff = (size_t)b * T_ * D_ + (size_t)h * HD_;

    {
        const float* Qg = g_Q + headoff + (size_t)q0 * D_;
#pragma unroll
        for (int u = 0; u < 16; u++) {
            int idx = u*256 + tid;
            int r = idx >> 6, c2 = idx & 63;
            float2 v = *reinterpret_cast<const float2*>(Qg + (size_t)r * D_ + 2*c2);
            Qs[r*QK_STR + 2*c2]     = v.x * SCALE_;
            Qs[r*QK_STR + 2*c2 + 1] = v.y * SCALE_;
        }
    }

    unsigned long long o2[4][4];
    float m[4], lsum[4];
#pragma unroll
    for (int i = 0; i < 4; i++) {
        m[i] = -1e30f; lsum[i] = 0.f;
#pragma unroll
        for (int j = 0; j < 4; j++) o2[i][j] = 0ull;
    }

    for (int jb = 0; jb <= qb; jb++) {
        __syncthreads();
        {
            const float* Kg = g_K + headoff + (size_t)jb * 64 * D_;
            const float* Vg = g_V + headoff + (size_t)jb * 64 * D_;
#pragma unroll
            for (int u = 0; u < 16; u++) {
                int idx = u*256 + tid;
                int r = idx >> 6, c2 = idx & 63;
                float2 v = *reinterpret_cast<const float2*>(Kg + (size_t)r * D_ + 2*c2);
                Ks[r*QK_STR + 2*c2]     = v.x;
                Ks[r*QK_STR + 2*c2 + 1] = v.y;
            }
#pragma unroll
            for (int u = 0; u < 8; u++) {
                int idx = u*256 + tid;
                int r = idx >> 5, c4 = idx & 31;
                *reinterpret_cast<float4*>(&Vs[r*128 + 4*c4]) =
                    *reinterpret_cast<const float4*>(Vg + (size_t)r * D_ + 4*c4);
            }
        }
        __syncthreads();

        unsigned long long s2[4][4];
#pragma unroll
        for (int i = 0; i < 4; i++)
#pragma unroll
            for (int j = 0; j < 4; j++) s2[i][j] = 0ull;

#pragma unroll 4
        for (int kk = 0; kk < 64; kk++) {
            unsigned long long qa[4], kb[4];
#pragma unroll
            for (int i = 0; i < 4; i++)
                qa[i] = *reinterpret_cast<const unsigned long long*>(&Qs[(4*ty + i)*QK_STR + 2*kk]);
#pragma unroll
            for (int j = 0; j < 4; j++)
                kb[j] = *reinterpret_cast<const unsigned long long*>(&Ks[(4*tx + j)*QK_STR + 2*kk]);
#pragma unroll
            for (int i = 0; i < 4; i++)
#pragma unroll
                for (int j = 0; j < 4; j++)
                    ffma2(s2[i][j], qa[i], kb[j]);
        }

        float s[4][4];
#pragma unroll
        for (int i = 0; i < 4; i++)
#pragma unroll
            for (int j = 0; j < 4; j++) {
                float2 p = unpk(s2[i][j]);
                s[i][j] = p.x + p.y;
            }

        if (jb == qb) {
#pragma unroll
            for (int i = 0; i < 4; i++)
#pragma unroll
                for (int j = 0; j < 4; j++)
                    if (4*tx + j > 4*ty + i) s[i][j] = -1e30f;
        }

#pragma unroll
        for (int i = 0; i < 4; i++) {
            float rmax = fmaxf(fmaxf(s[i][0], s[i][1]), fmaxf(s[i][2], s[i][3]));
#pragma unroll
            for (int off = 1; off < 16; off <<= 1)
                rmax = fmaxf(rmax, __shfl_xor_sync(0xffffffffu, rmax, off));
            float mn   = fmaxf(m[i], rmax);
            float corr = __expf(m[i] - mn);
            float p0 = __expf(s[i][0] - mn);
            float p1 = __expf(s[i][1] - mn);
            float p2 = __expf(s[i][2] - mn);
            float p3 = __expf(s[i][3] - mn);
            float rsum = p0 + p1 + p2 + p3;
#pragma unroll
            for (int off = 1; off < 16; off <<= 1)
                rsum += __shfl_xor_sync(0xffffffffu, rsum, off);
            lsum[i] = lsum[i]*corr + rsum;
            m[i] = mn;
            unsigned long long cd = dup2(corr);
#pragma unroll
            for (int j = 0; j < 4; j++) o2[i][j] = fmul2(o2[i][j], cd);

            float* srow = &Sd[(4*ty + i)*QK_STR];
            *reinterpret_cast<unsigned long long*>(&srow[2*(4*tx + 0)]) = dup2(p0);
            *reinterpret_cast<unsigned long long*>(&srow[2*(4*tx + 1)]) = dup2(p1);
            *reinterpret_cast<unsigned long long*>(&srow[2*(4*tx + 2)]) = dup2(p2);
            *reinterpret_cast<unsigned long long*>(&srow[2*(4*tx + 3)]) = dup2(p3);
        }
        __syncthreads();

#pragma unroll 2
        for (int kk = 0; kk < 64; kk++) {
            unsigned long long pd[4];
#pragma unroll
            for (int i = 0; i < 4; i++)
                pd[i] = *reinterpret_cast<const unsigned long long*>(&Sd[(4*ty + i)*QK_STR + 2*kk]);
            ulonglong2 vA = *reinterpret_cast<const ulonglong2*>(&Vs[kk*128 + 4*tx]);
            ulonglong2 vB = *reinterpret_cast<const ulonglong2*>(&Vs[kk*128 + 64 + 4*tx]);
#pragma unroll
            for (int i = 0; i < 4; i++) {
                ffma2(o2[i][0], pd[i], vA.x);
                ffma2(o2[i][1], pd[i], vA.y);
                ffma2(o2[i][2], pd[i], vB.x);
                ffma2(o2[i][3], pd[i], vB.y);
            }
        }
    }

    float* Og = g_AO + headoff + (size_t)q0 * D_;
#pragma unroll
    for (int i = 0; i < 4; i++) {
        float inv = 1.0f / lsum[i];
        int r = 4*ty + i;
#pragma unroll
        for (int half = 0; half < 2; half++) {
            int c = half ? (64 + 4*tx) : (4*tx);
            float2 p0 = unpk(o2[i][half*2 + 0]);
            float2 p1 = unpk(o2[i][half*2 + 1]);
            float4 v = make_float4(p0.x*inv, p0.y*inv, p1.x*inv, p1.y*inv);
            *reinterpret_cast<float4*>(Og + (size_t)r * D_ + c) = v;
        }
    }
}

// ---------------- launch ----------------
extern "C" void kernel_launch(void* const* d_in, const int* in_sizes, int n_in,
                              void* d_out, int out_size)
{
    (void)in_sizes; (void)n_in; (void)out_size;
    const float* x  = (const float*)d_in[0];
    const float* Wq = (const float*)d_in[1];
    const float* Wk = (const float*)d_in[2];
    const float* Wv = (const float*)d_in[3];
    const float* Wo = (const float*)d_in[4];
    const float* bo = (const float*)d_in[5];
    float* out = (float*)d_out;

    const int attn_smem = ATTN_SMEM_FLOATS * (int)sizeof(float);
    cudaFuncSetAttribute(attn_kernel, cudaFuncAttributeMaxDynamicSharedMemorySize, attn_smem);
    cudaFuncSetAttribute(gemm_qkv_tc, cudaFuncAttributeMaxDynamicSharedMemorySize, GSMEM_TOT);
    cudaFuncSetAttribute(gemm_out_tc, cudaFuncAttributeMaxDynamicSharedMemorySize, GSMEM_TOT);

    const int n4blocks = (int)(NELEM / 4 / 256);     // 16384
    fsplit_x<<<n4blocks, 256>>>(x);
    wsplit<<<dim3(64, 64, 4), 256>>>(Wq, Wk, Wv, Wo);
    gemm_qkv_tc<<<dim3(D_/128, NTOK/128, 3), 512, GSMEM_TOT>>>();
    attn_kernel<<<dim3(T_/64, B_*H_), 256, attn_smem>>>();
    fsplit_ao<<<n4blocks, 256>>>();
    gemm_out_tc<<<dim3(D_/128, NTOK/128), 512, GSMEM_TOT>>>(bo, out);
}

// round 8
// speedup vs baseline: 5.2320x; 1.7641x over previous
#include <cuda_runtime.h>
#include <cuda_bf16.h>
#include <cstdint>

#define B_   4
#define T_   2048
#define D_   2048
#define H_   16
#define HD_  128
#define NTOK (B_*T_)
#define NELEM ((size_t)NTOK*D_)
#define WELEM ((size_t)D_*D_)

// log2(e)/sqrt(128): folded into Q so softmax uses exp2
#define QSCALE 0.12751743f

// ---------------- device scratch ----------------
__device__ __nv_bfloat16 g_xhi[NELEM];
__device__ __nv_bfloat16 g_xlo[NELEM];
__device__ __nv_bfloat16 g_qh [NELEM];
__device__ __nv_bfloat16 g_ql [NELEM];
__device__ __nv_bfloat16 g_kh [NELEM];
__device__ __nv_bfloat16 g_kl [NELEM];
__device__ __nv_bfloat16 g_vh [NELEM];
__device__ __nv_bfloat16 g_vl [NELEM];
__device__ __nv_bfloat16 g_aohi[NELEM];
__device__ __nv_bfloat16 g_aolo[NELEM];
__device__ __nv_bfloat16 g_wth[4*WELEM];   // transposed hi: [which][N][K]
__device__ __nv_bfloat16 g_wtl[4*WELEM];   // transposed lo

// ---------------- PTX helpers (compute_103-safe) ----------------
__device__ __forceinline__ uint32_t smem_u32(const void* p) {
    uint32_t a;
    asm("{ .reg .u64 t; cvta.to.shared.u64 t, %1; cvt.u32.u64 %0, t; }" : "=r"(a) : "l"(p));
    return a;
}
__device__ __forceinline__ void cp16(uint32_t sa, const void* ga) {
    asm volatile("cp.async.ca.shared.global [%0], [%1], 16;" :: "r"(sa), "l"(ga));
}
__device__ __forceinline__ void cp_commit() {
    asm volatile("cp.async.commit_group;" ::: "memory");
}
template <int N>
__device__ __forceinline__ void cp_wait() {
    asm volatile("cp.async.wait_group %0;" :: "n"(N) : "memory");
}
__device__ __forceinline__ void ldsm4(uint32_t* r, uint32_t addr) {
    asm volatile("ldmatrix.sync.aligned.m8n8.x4.shared.b16 {%0,%1,%2,%3}, [%4];"
                 : "=r"(r[0]), "=r"(r[1]), "=r"(r[2]), "=r"(r[3]) : "r"(addr));
}
__device__ __forceinline__ void ldsm4t(uint32_t* r, uint32_t addr) {
    asm volatile("ldmatrix.sync.aligned.m8n8.x4.trans.shared.b16 {%0,%1,%2,%3}, [%4];"
                 : "=r"(r[0]), "=r"(r[1]), "=r"(r[2]), "=r"(r[3]) : "r"(addr));
}
__device__ __forceinline__ void mma_bf16(float* d, const uint32_t* a, uint32_t b0, uint32_t b1) {
    asm volatile("mma.sync.aligned.m16n8k16.row.col.f32.bf16.bf16.f32 "
                 "{%0,%1,%2,%3}, {%4,%5,%6,%7}, {%8,%9}, {%0,%1,%2,%3};"
                 : "+f"(d[0]), "+f"(d[1]), "+f"(d[2]), "+f"(d[3])
                 : "r"(a[0]), "r"(a[1]), "r"(a[2]), "r"(a[3]), "r"(b0), "r"(b1));
}
// split (x,y) -> packed bf16x2 hi and lo residual (x -> low half)
__device__ __forceinline__ void split_pack(float x, float y, uint32_t& h, uint32_t& l) {
    __nv_bfloat16 hx = __float2bfloat16(x), hy = __float2bfloat16(y);
    float rx = x - __bfloat162float(hx), ry = y - __bfloat162float(hy);
    __nv_bfloat162 hh; hh.x = hx; hh.y = hy;
    __nv_bfloat162 ll = __float22bfloat162_rn(make_float2(rx, ry));
    h = *reinterpret_cast<uint32_t*>(&hh);
    l = *reinterpret_cast<uint32_t*>(&ll);
}

// ---------------- fp32 -> bf16 hi/lo split of x ----------------
__device__ __forceinline__ void split1(float v, __nv_bfloat16& h, __nv_bfloat16& l) {
    h = __float2bfloat16(v);
    l = __float2bfloat16(v - __bfloat162float(h));
}
__global__ void fsplit_x(const float* __restrict__ in) {
    size_t i = (size_t)(blockIdx.x * blockDim.x + threadIdx.x) * 4;
    float4 v = *reinterpret_cast<const float4*>(in + i);
    __nv_bfloat16 h0,h1,h2,h3,l0,l1,l2,l3;
    split1(v.x,h0,l0); split1(v.y,h1,l1); split1(v.z,h2,l2); split1(v.w,h3,l3);
    __nv_bfloat162* hp = reinterpret_cast<__nv_bfloat162*>(g_xhi + i);
    __nv_bfloat162* lp = reinterpret_cast<__nv_bfloat162*>(g_xlo + i);
    __nv_bfloat162 a; a.x=h0; a.y=h1; hp[0]=a; a.x=h2; a.y=h3; hp[1]=a;
    __nv_bfloat162 b; b.x=l0; b.y=l1; lp[0]=b; b.x=l2; b.y=l3; lp[1]=b;
}

// ---------------- weight transpose + split: W[K,N] -> Wt hi/lo [N,K] ----------------
__global__ void wsplit(const float* __restrict__ Wq, const float* __restrict__ Wk,
                       const float* __restrict__ Wv, const float* __restrict__ Wo) {
    const float* W;
    int z = blockIdx.z;
    if (z == 0) W = Wq; else if (z == 1) W = Wk; else if (z == 2) W = Wv; else W = Wo;
    __nv_bfloat16* th = g_wth + (size_t)z * WELEM;
    __nv_bfloat16* tl = g_wtl + (size_t)z * WELEM;

    __shared__ float t[32][33];
    int tx = threadIdx.x & 31, ty = threadIdx.x >> 5;   // 32 x 8
    int x0 = blockIdx.x * 32, y0 = blockIdx.y * 32;
#pragma unroll
    for (int i = 0; i < 4; i++)
        t[ty + 8*i][tx] = W[(size_t)(y0 + ty + 8*i) * D_ + x0 + tx];
    __syncthreads();
#pragma unroll
    for (int i = 0; i < 4; i++) {
        int n = x0 + ty + 8*i, k = y0 + tx;
        float v = t[tx][ty + 8*i];
        __nv_bfloat16 h, l;
        split1(v, h, l);
        th[(size_t)n * D_ + k] = h;
        tl[(size_t)n * D_ + k] = l;
    }
}

// ---------------- HMMA GEMM core ----------------
// C[128,128] = (Ah+Al)[128,2048] @ (Bh+Bl)t ; 512 thr, 16 warps (4x4), warp 32x32.
#define GST_B    144
#define GTILE_B  (128*GST_B)
#define GSTAGE_B (4*GTILE_B)
#define GSMEM_TOT (2*GSTAGE_B)            // 147456

__device__ __forceinline__
void gemm_hmma_core(const __nv_bfloat16* __restrict__ Ah, const __nv_bfloat16* __restrict__ Al,
                    const __nv_bfloat16* __restrict__ Bh, const __nv_bfloat16* __restrict__ Bl,
                    float* __restrict__ Cf, const float* __restrict__ bias,
                    __nv_bfloat16* __restrict__ oh, __nv_bfloat16* __restrict__ ol, float oscale,
                    int bx, int by)
{
    extern __shared__ char smem[];
    const uint32_t sb = smem_u32(smem);
    const int tid = threadIdx.x;
    const int wid = tid >> 5, l = tid & 31;
    const int wm = wid >> 2, wn = wid & 3;
    const int m0 = by * 128, n0 = bx * 128;

    const __nv_bfloat16* src[4] = {
        Ah + (size_t)m0 * D_, Al + (size_t)m0 * D_,
        Bh + (size_t)n0 * D_, Bl + (size_t)n0 * D_ };

    const int a_row = (l & 7) + ((l >> 3) & 1) * 8;
    const int a_c8  = ((l >> 4) & 1) * 8;
    const int b_row = (l & 7) + ((l >> 4) & 1) * 8;
    const int b_c8  = ((l >> 3) & 1) * 8;
    uint32_t aoff[2], boff[2];
#pragma unroll
    for (int i = 0; i < 2; i++) aoff[i] = (32*wm + 16*i + a_row) * GST_B + a_c8 * 2;
#pragma unroll
    for (int p = 0; p < 2; p++) boff[p] = (32*wn + 16*p + b_row) * GST_B + b_c8 * 2;

    float d[2][4][4];
#pragma unroll
    for (int i = 0; i < 2; i++)
#pragma unroll
        for (int j = 0; j < 4; j++)
#pragma unroll
            for (int q = 0; q < 4; q++) d[i][j][q] = 0.f;

    auto issue = [&](int ch) {
        const uint32_t s0 = sb + (ch & 1) * GSTAGE_B;
        const int k0 = ch * 64;
#pragma unroll
        for (int a = 0; a < 4; a++) {
#pragma unroll
            for (int h = 0; h < 2; h++) {
                int s = tid + h * 512;
                int row = s >> 3, c = s & 7;
                cp16(s0 + a*GTILE_B + row*GST_B + c*16,
                     src[a] + (size_t)row * D_ + k0 + c*8);
            }
        }
        cp_commit();
    };

    issue(0);
#pragma unroll 1
    for (int ch = 0; ch < 32; ch++) {
        if (ch < 31) { issue(ch + 1); cp_wait<1>(); }
        else         { cp_wait<0>(); }
        __syncthreads();

        const uint32_t s0 = sb + (ch & 1) * GSTAGE_B;
#pragma unroll
        for (int ks = 0; ks < 4; ks++) {
            const int kb = ks * 32;
            uint32_t AH[2][4], AL[2][4], BH[2][4], BL[2][4];
#pragma unroll
            for (int i = 0; i < 2; i++) {
                ldsm4(AH[i], s0 +              aoff[i] + kb);
                ldsm4(AL[i], s0 +   GTILE_B +  aoff[i] + kb);
            }
#pragma unroll
            for (int p = 0; p < 2; p++) {
                ldsm4(BH[p], s0 + 2*GTILE_B + boff[p] + kb);
                ldsm4(BL[p], s0 + 3*GTILE_B + boff[p] + kb);
            }
#pragma unroll
            for (int i = 0; i < 2; i++) {
#pragma unroll
                for (int j = 0; j < 4; j++) {
                    const int p = j >> 1, r = (j & 1) * 2;
                    mma_bf16(d[i][j], AH[i], BH[p][r], BH[p][r+1]);
                    mma_bf16(d[i][j], AH[i], BL[p][r], BL[p][r+1]);
                    mma_bf16(d[i][j], AL[i], BH[p][r], BH[p][r+1]);
                }
            }
        }
        __syncthreads();
    }

    const int gid = l >> 2, tig = l & 3;
#pragma unroll
    for (int i = 0; i < 2; i++) {
#pragma unroll
        for (int j = 0; j < 4; j++) {
            int row = m0 + 32*wm + 16*i + gid;
            int col = n0 + 32*wn + 8*j + 2*tig;
            if (Cf) {
                float2 v0 = make_float2(d[i][j][0], d[i][j][1]);
                float2 v1 = make_float2(d[i][j][2], d[i][j][3]);
                const float2 bb = *reinterpret_cast<const float2*>(bias + col);
                v0.x += bb.x; v0.y += bb.y;
                v1.x += bb.x; v1.y += bb.y;
                *reinterpret_cast<float2*>(Cf + (size_t)row * D_ + col)       = v0;
                *reinterpret_cast<float2*>(Cf + (size_t)(row + 8) * D_ + col) = v1;
            } else {
                uint32_t hh, ll;
                split_pack(d[i][j][0]*oscale, d[i][j][1]*oscale, hh, ll);
                *reinterpret_cast<uint32_t*>(oh + (size_t)row * D_ + col) = hh;
                *reinterpret_cast<uint32_t*>(ol + (size_t)row * D_ + col) = ll;
                split_pack(d[i][j][2]*oscale, d[i][j][3]*oscale, hh, ll);
                *reinterpret_cast<uint32_t*>(oh + (size_t)(row + 8) * D_ + col) = hh;
                *reinterpret_cast<uint32_t*>(ol + (size_t)(row + 8) * D_ + col) = ll;
            }
        }
    }
}

__global__ __launch_bounds__(512, 1)
void gemm_qkv_tc() {
    const int z = blockIdx.z;
    __nv_bfloat16 *oh, *ol; float sc;
    if (z == 0)      { oh = g_qh; ol = g_ql; sc = QSCALE; }
    else if (z == 1) { oh = g_kh; ol = g_kl; sc = 1.f; }
    else             { oh = g_vh; ol = g_vl; sc = 1.f; }
    gemm_hmma_core(g_xhi, g_xlo, g_wth + (size_t)z * WELEM, g_wtl + (size_t)z * WELEM,
                   nullptr, nullptr, oh, ol, sc, blockIdx.x, blockIdx.y);
}
__global__ __launch_bounds__(512, 1)
void gemm_out_tc(const float* __restrict__ bo, float* __restrict__ out) {
    gemm_hmma_core(g_aohi, g_aolo, g_wth + 3 * WELEM, g_wtl + 3 * WELEM,
                   out, bo, nullptr, nullptr, 1.f, blockIdx.x, blockIdx.y);
}

// ---------------- HMMA flash attention (causal) ----------------
// CTA: 128 q-rows x one head. 8 warps, warp = m16. BN=64 keys/iter.
// 2-stage cp.async KV (Kh,Kl,Vh,Vl). Softmax in fragments (exp2; scale folded into Q).
#define AST       272                      // smem row stride bytes (conflict-free ldmatrix)
#define AQ_TILE_B (128*AST)                // 34816
#define AKV_TILE_B (64*AST)                // 17408
#define AKV_STAGE_B (4*AKV_TILE_B)         // 69632
#define ASMEM_TOT (2*AQ_TILE_B + 2*AKV_STAGE_B)   // 208896

__global__ __launch_bounds__(256, 1)
void attn_hmma()
{
    extern __shared__ char smem[];
    const uint32_t sb = smem_u32(smem);
    const int tid = threadIdx.x;
    const int wid = tid >> 5, l = tid & 31;
    const int g = l >> 2, t = l & 3;

    const int bid = blockIdx.x;
    const int qb = 15 - (bid >> 6);        // heavy tiles first
    const int bh = bid & 63;
    const int b = bh >> 4, h = bh & 15;
    const int q0 = qb * 128;
    const int nkb = 2*qb + 2;
    const size_t qbase = ((size_t)(b*T_ + q0)) * D_ + h * HD_;
    const size_t kbase = ((size_t)(b*T_)) * D_ + h * HD_;

    const uint32_t sQh = sb, sQl = sb + AQ_TILE_B;
    const uint32_t sKV = sb + 2*AQ_TILE_B;

    // Q tiles (hi/lo) via cp.async; joins first commit group
#pragma unroll
    for (int i = 0; i < 8; i++) {
        int idx = tid + i*256;
        int r = idx >> 4, c = idx & 15;
        cp16(sQh + r*AST + c*16, g_qh + qbase + (size_t)r * D_ + c*8);
        cp16(sQl + r*AST + c*16, g_ql + qbase + (size_t)r * D_ + c*8);
    }

    auto issue = [&](int kb) {
        const uint32_t s0 = sKV + (kb & 1) * AKV_STAGE_B;
        const size_t koff = kbase + (size_t)kb * 64 * D_;
        const __nv_bfloat16* srcs[4] = { g_kh + koff, g_kl + koff, g_vh + koff, g_vl + koff };
#pragma unroll
        for (int a = 0; a < 4; a++) {
#pragma unroll
            for (int i = 0; i < 4; i++) {
                int idx = tid + i*256;
                int r = idx >> 4, c = idx & 15;
                cp16(s0 + a*AKV_TILE_B + r*AST + c*16, srcs[a] + (size_t)r * D_ + c*8);
            }
        }
        cp_commit();
    };
    issue(0);

    // ldmatrix lane address components
    const int lr = l & 7, lb3 = (l >> 3) & 1, lb4 = (l >> 4) & 1;
    const uint32_t q_off = (16*wid + lr + lb3*8) * AST + lb4*16;   // + ks*32
    const uint32_t k_off = (lr + lb4*8) * AST + lb3*16;            // + jj*16*AST + ks*32
    const uint32_t v_off = (lr + lb3*8) * AST + lb4*16;            // + ks2*16*AST + jj*32

    float O[16][4];
#pragma unroll
    for (int i = 0; i < 16; i++)
#pragma unroll
        for (int q = 0; q < 4; q++) O[i][q] = 0.f;
    float mrow[2] = {-1e30f, -1e30f}, lrow[2] = {0.f, 0.f};

#pragma unroll 1
    for (int kb = 0; kb < nkb; kb++) {
        if (kb + 1 < nkb) { issue(kb + 1); cp_wait<1>(); }
        else              { cp_wait<0>(); }
        __syncthreads();

        const uint32_t s0 = sKV + (kb & 1) * AKV_STAGE_B;
        const uint32_t sKh = s0, sKl = s0 + AKV_TILE_B;
        const uint32_t sVh = s0 + 2*AKV_TILE_B, sVl = s0 + 3*AKV_TILE_B;

        // ---- S = Q K^T (3-pass hi/lo) ----
        float S[8][4];
#pragma unroll
        for (int j = 0; j < 8; j++)
#pragma unroll
            for (int q = 0; q < 4; q++) S[j][q] = 0.f;

#pragma unroll
        for (int ks = 0; ks < 8; ks++) {
            uint32_t QH[4], QL[4];
            ldsm4(QH, sQh + q_off + ks*32);
            ldsm4(QL, sQl + q_off + ks*32);
#pragma unroll
            for (int jj = 0; jj < 4; jj++) {
                uint32_t KH[4], KL[4];
                ldsm4(KH, sKh + k_off + jj*(16*AST) + ks*32);
                ldsm4(KL, sKl + k_off + jj*(16*AST) + ks*32);
                mma_bf16(S[2*jj],   QH, KH[0], KH[1]);
                mma_bf16(S[2*jj],   QH, KL[0], KL[1]);
                mma_bf16(S[2*jj],   QL, KH[0], KH[1]);
                mma_bf16(S[2*jj+1], QH, KH[2], KH[3]);
                mma_bf16(S[2*jj+1], QH, KL[2], KL[3]);
                mma_bf16(S[2*jj+1], QL, KH[2], KH[3]);
            }
        }

        // ---- causal mask (last two blocks only) ----
        if (kb >= 2*qb) {
            const int row0 = q0 + 16*wid + g;
            const int cb = kb*64 + 2*t;
#pragma unroll
            for (int j = 0; j < 8; j++) {
                int c0 = cb + 8*j;
                if (c0     > row0)     S[j][0] = -1e30f;
                if (c0 + 1 > row0)     S[j][1] = -1e30f;
                if (c0     > row0 + 8) S[j][2] = -1e30f;
                if (c0 + 1 > row0 + 8) S[j][3] = -1e30f;
            }
        }

        // ---- online softmax (exp2 domain) ----
#pragma unroll
        for (int rr = 0; rr < 2; rr++) {
            float mx = -1e30f;
#pragma unroll
            for (int j = 0; j < 8; j++)
                mx = fmaxf(mx, fmaxf(S[j][2*rr], S[j][2*rr+1]));
            mx = fmaxf(mx, __shfl_xor_sync(0xffffffffu, mx, 1));
            mx = fmaxf(mx, __shfl_xor_sync(0xffffffffu, mx, 2));
            float mn = fmaxf(mrow[rr], mx);
            float corr = exp2f(mrow[rr] - mn);
            mrow[rr] = mn;
            float sum = 0.f;
#pragma unroll
            for (int j = 0; j < 8; j++) {
                float p0 = exp2f(S[j][2*rr]   - mn);
                float p1 = exp2f(S[j][2*rr+1] - mn);
                S[j][2*rr] = p0; S[j][2*rr+1] = p1;
                sum += p0 + p1;
            }
            sum += __shfl_xor_sync(0xffffffffu, sum, 1);
            sum += __shfl_xor_sync(0xffffffffu, sum, 2);
            lrow[rr] = lrow[rr]*corr + sum;
#pragma unroll
            for (int jt = 0; jt < 16; jt++) {
                O[jt][2*rr]   *= corr;
                O[jt][2*rr+1] *= corr;
            }
        }

        // ---- pack P into A-fragments (hi/lo) ----
        uint32_t PH[4][4], PL[4][4];
#pragma unroll
        for (int ks2 = 0; ks2 < 4; ks2++) {
#pragma unroll
            for (int half = 0; half < 2; half++) {
                const int tile = 2*ks2 + half;
                split_pack(S[tile][0], S[tile][1], PH[ks2][2*half],   PL[ks2][2*half]);
                split_pack(S[tile][2], S[tile][3], PH[ks2][2*half+1], PL[ks2][2*half+1]);
            }
        }

        // ---- O += P V (3-pass hi/lo, V via ldmatrix.trans) ----
#pragma unroll
        for (int ks2 = 0; ks2 < 4; ks2++) {
#pragma unroll
            for (int jj = 0; jj < 8; jj++) {
                uint32_t VH[4], VL[4];
                ldsm4t(VH, sVh + v_off + ks2*(16*AST) + jj*32);
                ldsm4t(VL, sVl + v_off + ks2*(16*AST) + jj*32);
                mma_bf16(O[2*jj],   PH[ks2], VH[0], VH[1]);
                mma_bf16(O[2*jj],   PH[ks2], VL[0], VL[1]);
                mma_bf16(O[2*jj],   PL[ks2], VH[0], VH[1]);
                mma_bf16(O[2*jj+1], PH[ks2], VH[2], VH[3]);
                mma_bf16(O[2*jj+1], PH[ks2], VL[2], VL[3]);
                mma_bf16(O[2*jj+1], PL[ks2], VH[2], VH[3]);
            }
        }
        __syncthreads();   // protect stage buffers before next issue
    }

    // ---- normalize + split-write AO (bf16 hi/lo) ----
    const float inv0 = 1.f / lrow[0], inv1 = 1.f / lrow[1];
    const int r0 = q0 + 16*wid + g;
    const size_t off0 = ((size_t)(b*T_) + r0) * D_ + h * HD_ + 2*t;
#pragma unroll
    for (int jt = 0; jt < 16; jt++) {
        uint32_t hh, ll;
        split_pack(O[jt][0]*inv0, O[jt][1]*inv0, hh, ll);
        *reinterpret_cast<uint32_t*>(g_aohi + off0 + 8*jt) = hh;
        *reinterpret_cast<uint32_t*>(g_aolo + off0 + 8*jt) = ll;
        split_pack(O[jt][2]*inv1, O[jt][3]*inv1, hh, ll);
        *reinterpret_cast<uint32_t*>(g_aohi + off0 + 8*(size_t)D_ + 8*jt) = hh;
        *reinterpret_cast<uint32_t*>(g_aolo + off0 + 8*(size_t)D_ + 8*jt) = ll;
    }
}

// ---------------- launch ----------------
extern "C" void kernel_launch(void* const* d_in, const int* in_sizes, int n_in,
                              void* d_out, int out_size)
{
    (void)in_sizes; (void)n_in; (void)out_size;
    const float* x  = (const float*)d_in[0];
    const float* Wq = (const float*)d_in[1];
    const float* Wk = (const float*)d_in[2];
    const float* Wv = (const float*)d_in[3];
    const float* Wo = (const float*)d_in[4];
    const float* bo = (const float*)d_in[5];
    float* out = (float*)d_out;

    cudaFuncSetAttribute(gemm_qkv_tc, cudaFuncAttributeMaxDynamicSharedMemorySize, GSMEM_TOT);
    cudaFuncSetAttribute(gemm_out_tc, cudaFuncAttributeMaxDynamicSharedMemorySize, GSMEM_TOT);
    cudaFuncSetAttribute(attn_hmma,   cudaFuncAttributeMaxDynamicSharedMemorySize, ASMEM_TOT);

    const int n4blocks = (int)(NELEM / 4 / 256);     // 16384
    fsplit_x<<<n4blocks, 256>>>(x);
    wsplit<<<dim3(64, 64, 4), 256>>>(Wq, Wk, Wv, Wo);
    gemm_qkv_tc<<<dim3(D_/128, NTOK/128, 3), 512, GSMEM_TOT>>>();
    attn_hmma<<<1024, 256, ASMEM_TOT>>>();
    gemm_out_tc<<<dim3(D_/128, NTOK/128), 512, GSMEM_TOT>>>(bo, out);
}